// round 17
// baseline (speedup 1.0000x reference)
#include <cuda_runtime.h>
#include <cuda_bf16.h>
#include <math.h>
#include <stdint.h>

#define BATCH   2
#define SEQ     2048
#define HIDDEN  2048
#define NH      16
#define NKV     4
#define HD      128
#define MTOT    (BATCH*SEQ)      // 4096
#define QDIM    (NH*HD)          // 2048
#define KVDIM   (NKV*HD)         // 512
#define QKVDIM  (QDIM+2*KVDIM)   // 3072
#define ATTN_SCALE 0.08838834764831845f
#define CS (ATTN_SCALE * 1.4426950408889634f)   // scale * log2(e)

// ---------------- scratch (device globals; no allocation allowed) ----------
__device__ __nv_bfloat16 g_Xh[(size_t)MTOT*HIDDEN];
__device__ __nv_bfloat16 g_Xl[(size_t)MTOT*HIDDEN];
__device__ __nv_bfloat16 g_Wh[(size_t)QKVDIM*HIDDEN];
__device__ __nv_bfloat16 g_Wl[(size_t)QKVDIM*HIDDEN];
__device__ __nv_bfloat16 g_WOh[(size_t)HIDDEN*QDIM];
__device__ __nv_bfloat16 g_WOl[(size_t)HIDDEN*QDIM];
__device__ __nv_bfloat16 g_QKVh[(size_t)MTOT*QKVDIM];   // 25 MB
__device__ __nv_bfloat16 g_QKVl[(size_t)MTOT*QKVDIM];
__device__ __nv_bfloat16 g_AOh[(size_t)MTOT*QDIM];
__device__ __nv_bfloat16 g_AOl[(size_t)MTOT*QDIM];

// ================= helpers ==================================================
__device__ __forceinline__ void ldsm_x4(uint32_t* r, uint32_t addr) {
    asm volatile("ldmatrix.sync.aligned.m8n8.x4.shared.b16 {%0,%1,%2,%3}, [%4];"
                 : "=r"(r[0]), "=r"(r[1]), "=r"(r[2]), "=r"(r[3]) : "r"(addr));
}
__device__ __forceinline__ void ldsm_x4_t(uint32_t* r, uint32_t addr) {
    asm volatile("ldmatrix.sync.aligned.m8n8.x4.trans.shared.b16 {%0,%1,%2,%3}, [%4];"
                 : "=r"(r[0]), "=r"(r[1]), "=r"(r[2]), "=r"(r[3]) : "r"(addr));
}
__device__ __forceinline__ void mma16816(float* d, const uint32_t* a, const uint32_t* b) {
    asm volatile("mma.sync.aligned.m16n8k16.row.col.f32.bf16.bf16.f32 "
                 "{%0,%1,%2,%3},{%4,%5,%6,%7},{%8,%9},{%0,%1,%2,%3};"
                 : "+f"(d[0]), "+f"(d[1]), "+f"(d[2]), "+f"(d[3])
                 : "r"(a[0]), "r"(a[1]), "r"(a[2]), "r"(a[3]), "r"(b[0]), "r"(b[1]));
}
__device__ __forceinline__ uint32_t smem_u32(const void* p) {
    return (uint32_t)__cvta_generic_to_shared(p);
}
__device__ __forceinline__ float ex2f(float x) {
    float r; asm("ex2.approx.ftz.f32 %0, %1;" : "=f"(r) : "f"(x)); return r;
}
__device__ __forceinline__ uint32_t packbf(float lo, float hi) {  // lo -> low half
    uint32_t d; asm("cvt.rn.bf16x2.f32 %0, %1, %2;" : "=r"(d) : "f"(hi), "f"(lo)); return d;
}
__device__ __forceinline__ float bf16rt(float x) {
    return __bfloat162float(__float2bfloat16(x));
}
#define CP_ASYNC16(sa, gp) \
    asm volatile("cp.async.cg.shared.global [%0], [%1], 16;" :: "r"(sa), "l"(gp))
#define CP_COMMIT() asm volatile("cp.async.commit_group;" ::: "memory")
#define CP_WAIT0()  asm volatile("cp.async.wait_group 0;" ::: "memory")
#define CP_WAIT1()  asm volatile("cp.async.wait_group 1;" ::: "memory")

// ============ HMMA GEMM, 2-stage cp.async pipeline ==========================
// FUSE=false: plain C[M,N] fp32 store.
// FUSE=true : QKV epilogue — RoPE on Q/K sections, emit new_k/new_v,
//             write bf16 hi/lo QKV directly. (C/ldc unused.)
#define BK    32
#define SLD   40
#define TILE_HALVES  (128*SLD)
#define STAGE_HALVES (4*TILE_HALVES)
#define GEMM_SMEM    (2*STAGE_HALVES*2)   // 81920 bytes

template<bool FUSE>
__global__ void __launch_bounds__(256, 2) mma_gemm(
    const __nv_bfloat16* __restrict__ Ah, const __nv_bfloat16* __restrict__ Al,
    const __nv_bfloat16* __restrict__ Bh, const __nv_bfloat16* __restrict__ Bl,
    float* __restrict__ C, int ldc, int K,
    const float* __restrict__ freqs, float* __restrict__ outk, float* __restrict__ outv,
    __nv_bfloat16* __restrict__ Oh, __nv_bfloat16* __restrict__ Ol)
{
    extern __shared__ __nv_bfloat16 sm[];
    const int tid  = threadIdx.x;
    const int lane = tid & 31;
    const int wid  = tid >> 5;
    const int wr   = wid >> 2;
    const int wc   = wid & 3;

    float acc[4][4][4];
    #pragma unroll
    for (int m = 0; m < 4; m++)
        #pragma unroll
        for (int n = 0; n < 4; n++)
            #pragma unroll
            for (int i = 0; i < 4; i++) acc[m][n][i] = 0.f;

    const size_t arow0 = (size_t)blockIdx.y * 128;
    const size_t brow0 = (size_t)blockIdx.x * 128;

    const int a_r = lane & 15, a_c = ((lane >> 4) & 1) * 8;
    const int b_r = ((lane >> 4) & 1) * 8 + (lane & 7);   // n-pair ldsm_x4 pattern
    const int b_c = ((lane >> 3) & 1) * 8;
    const int nk = K / BK;

    auto issue_stage = [&](int sel, int k0) {
        __nv_bfloat16* base = sm + sel * STAGE_HALVES;
        const __nv_bfloat16* srcs[4] = { Ah + arow0*K + k0, Al + arow0*K + k0,
                                         Bh + brow0*K + k0, Bl + brow0*K + k0 };
        #pragma unroll
        for (int t = 0; t < 4; t++) {
            __nv_bfloat16* dst = base + t * TILE_HALVES;
            #pragma unroll
            for (int u = 0; u < 2; u++) {
                int idx = tid + u * 256;
                int r = idx >> 2, c = (idx & 3) * 8;
                CP_ASYNC16(smem_u32(dst + r*SLD + c), srcs[t] + (size_t)r*K + c);
            }
        }
        CP_COMMIT();
    };

    issue_stage(0, 0);
    for (int i = 0; i < nk; i++) {
        if (i + 1 < nk) { issue_stage((i + 1) & 1, (i + 1) * BK); CP_WAIT1(); }
        else            { CP_WAIT0(); }
        __syncthreads();

        __nv_bfloat16* base = sm + (i & 1) * STAGE_HALVES;
        __nv_bfloat16* bAh = base;
        __nv_bfloat16* bAl = base + 1*TILE_HALVES;
        __nv_bfloat16* bBh = base + 2*TILE_HALVES;
        __nv_bfloat16* bBl = base + 3*TILE_HALVES;

        #pragma unroll
        for (int kk = 0; kk < BK; kk += 16) {
            uint32_t bhf[4][2], blf[4][2];
            #pragma unroll
            for (int np = 0; np < 4; np += 2) {
                int row = wc * 32 + np * 8 + b_r;
                uint32_t t4[4];
                ldsm_x4(t4, smem_u32(bBh + row*SLD + kk + b_c));
                bhf[np][0] = t4[0]; bhf[np][1] = t4[1];
                bhf[np+1][0] = t4[2]; bhf[np+1][1] = t4[3];
                ldsm_x4(t4, smem_u32(bBl + row*SLD + kk + b_c));
                blf[np][0] = t4[0]; blf[np][1] = t4[1];
                blf[np+1][0] = t4[2]; blf[np+1][1] = t4[3];
            }
            #pragma unroll
            for (int m = 0; m < 4; m++) {
                uint32_t ah[4], al[4];
                int row = wr * 64 + m * 16 + a_r;
                ldsm_x4(ah, smem_u32(bAh + row*SLD + kk + a_c));
                ldsm_x4(al, smem_u32(bAl + row*SLD + kk + a_c));
                // pass-major: dependent MMAs to the same acc are distance-4 apart
                #pragma unroll
                for (int n = 0; n < 4; n++) mma16816(acc[m][n], ah, bhf[n]);
                #pragma unroll
                for (int n = 0; n < 4; n++) mma16816(acc[m][n], ah, blf[n]);
                #pragma unroll
                for (int n = 0; n < 4; n++) mma16816(acc[m][n], al, bhf[n]);
            }
        }
        __syncthreads();
    }

    const int r0 = lane >> 2, cbase = (lane & 3) * 2;
    #pragma unroll
    for (int m = 0; m < 4; m++) {
        size_t grow = arow0 + wr * 64 + m * 16 + r0;
        #pragma unroll
        for (int n = 0; n < 4; n++) {
            int gcol = (int)brow0 + wc * 32 + n * 8 + cbase;
            if (!FUSE) {
                *(float2*)(C + grow * ldc + gcol)       = make_float2(acc[m][n][0], acc[m][n][1]);
                *(float2*)(C + (grow + 8) * ldc + gcol) = make_float2(acc[m][n][2], acc[m][n][3]);
            } else {
                #pragma unroll
                for (int half = 0; half < 2; half++) {
                    size_t row = grow + half * 8;
                    float v0 = acc[m][n][half*2], v1 = acc[m][n][half*2 + 1];
                    float rx = v0, ry = v1;
                    if (gcol < QDIM + KVDIM) {          // Q or K: apply RoPE
                        int s = (int)(row & (SEQ - 1));
                        int fi = (gcol & (HD - 1)) >> 1;
                        float f = freqs[(size_t)s*64 + fi];
                        float sn, cc; sincosf(f, &sn, &cc);
                        rx = v0*cc - v1*sn;
                        ry = v0*sn + v1*cc;
                        if (gcol >= QDIM)               // K: emit new_k (fp32)
                            *(float2*)(outk + row*KVDIM + (gcol - QDIM)) = make_float2(rx, ry);
                    } else {                            // V: emit new_v (fp32)
                        *(float2*)(outv + row*KVDIM + (gcol - QDIM - KVDIM)) = make_float2(v0, v1);
                    }
                    *(uint32_t*)&Oh[row*QKVDIM + gcol] = packbf(bf16rt(rx), bf16rt(ry));
                    *(uint32_t*)&Ol[row*QKVDIM + gcol] = packbf(rx - bf16rt(rx), ry - bf16rt(ry));
                }
            }
        }
    }
}

// ---------------- fused fp32 -> bf16 hi/lo split of all 5 inputs -------------
#define N4_X   (MTOT*HIDDEN/4)       // 2097152
#define N4_WQ  (QDIM*HIDDEN/4)       // 1048576
#define N4_WKV (KVDIM*HIDDEN/4)      // 262144
#define N4_WO  (HIDDEN*QDIM/4)       // 1048576
#define N4_TOT (N4_X + N4_WQ + 2*N4_WKV + N4_WO)   // 4718592

__global__ void k_split_all(const float* __restrict__ x,  const float* __restrict__ wq,
                            const float* __restrict__ wk, const float* __restrict__ wv,
                            const float* __restrict__ wo,
                            __nv_bfloat16* __restrict__ Xh, __nv_bfloat16* __restrict__ Xl,
                            __nv_bfloat16* __restrict__ Wh, __nv_bfloat16* __restrict__ Wl,
                            __nv_bfloat16* __restrict__ WOh, __nv_bfloat16* __restrict__ WOl)
{
    int i = blockIdx.x * blockDim.x + threadIdx.x;
    if (i >= N4_TOT) return;
    const float* src; __nv_bfloat16 *hi, *lo; int j = i;
    if (j < N4_X)                       { src = x;  hi = Xh; lo = Xl; }
    else if ((j -= N4_X)  < N4_WQ)      { src = wq; hi = Wh; lo = Wl; }
    else if ((j -= N4_WQ) < N4_WKV)     { src = wk; hi = Wh + (size_t)QDIM*HIDDEN;
                                                    lo = Wl + (size_t)QDIM*HIDDEN; }
    else if ((j -= N4_WKV) < N4_WKV)    { src = wv; hi = Wh + (size_t)(QDIM+KVDIM)*HIDDEN;
                                                    lo = Wl + (size_t)(QDIM+KVDIM)*HIDDEN; }
    else                                { j -= N4_WKV; src = wo; hi = WOh; lo = WOl; }
    float4 v = ((const float4*)src)[j];
    uint2 hv, lv;
    hv.x = packbf(bf16rt(v.x), bf16rt(v.y));
    hv.y = packbf(bf16rt(v.z), bf16rt(v.w));
    lv.x = packbf(v.x - bf16rt(v.x), v.y - bf16rt(v.y));
    lv.y = packbf(v.z - bf16rt(v.z), v.w - bf16rt(v.w));
    ((uint2*)hi)[j] = hv;
    ((uint2*)lo)[j] = lv;
}

// ============ fused flash attention (HMMA, cp.async phase pipeline) ==========
#define TILE_B 34816     // 128 * 136 * 2 bytes
#define FLASH_SMEM (6 * TILE_B)

__global__ void __launch_bounds__(256, 1) k_flash(
    const __nv_bfloat16* __restrict__ QKVh, const __nv_bfloat16* __restrict__ QKVl,
    __nv_bfloat16* __restrict__ AOh, __nv_bfloat16* __restrict__ AOl)
{
    extern __shared__ char smraw[];
    typedef __nv_bfloat16 (*tile_t)[136];
    tile_t sQh = (tile_t)(smraw);
    tile_t sQl = (tile_t)(smraw + 1*TILE_B);
    tile_t sKh = (tile_t)(smraw + 2*TILE_B);
    tile_t sKl = (tile_t)(smraw + 3*TILE_B);
    tile_t sVh = (tile_t)(smraw + 4*TILE_B);
    tile_t sVl = (tile_t)(smraw + 5*TILE_B);

    const int qt = (int)gridDim.x - 1 - (int)blockIdx.x;   // heavy tiles first
    const int bh = blockIdx.y;
    const int b = bh >> 4, h = bh & 15, kh = h >> 2;
    const int tid = threadIdx.x, lane = tid & 31, wid = tid >> 5;

    auto load_tile = [&](tile_t dst, const __nv_bfloat16* src) {
        #pragma unroll
        for (int u = 0; u < 8; u++) {
            int i = tid + u * 256;
            int r = i >> 4, c = (i & 15) * 8;
            CP_ASYNC16(smem_u32(&dst[r][c]), src + (size_t)r*QKVDIM + c);
        }
    };

    const size_t qbase = ((size_t)(b*SEQ + qt*128))*QKVDIM + h*HD;
    load_tile(sQh, QKVh + qbase); load_tile(sQl, QKVl + qbase); CP_COMMIT();
    {
        const size_t kb = ((size_t)(b*SEQ))*QKVDIM + QDIM + kh*HD;
        load_tile(sKh, QKVh + kb); load_tile(sKl, QKVl + kb); CP_COMMIT();
        load_tile(sVh, QKVh + kb + KVDIM); load_tile(sVl, QKVl + kb + KVDIM); CP_COMMIT();
    }

    float oacc[16][4];
    #pragma unroll
    for (int n = 0; n < 16; n++)
        #pragma unroll
        for (int i = 0; i < 4; i++) oacc[n][i] = 0.f;
    float mi0 = -1e30f, mi1 = -1e30f, li0 = 0.f, li1 = 0.f;

    const int q_r  = wid*16 + (lane & 15);
    const int q_c  = (lane >> 4) * 8;
    const int k_ro = ((lane >> 4) & 1) * 8 + (lane & 7);
    const int k_co = ((lane >> 3) & 1) * 8;
    const int v_ro = ((lane >> 3) & 1) * 8 + (lane & 7);
    const int v_co = ((lane >> 4) & 1) * 8;
    const int r_lo = lane >> 2;
    const int c_lo = (lane & 3) * 2;

    for (int kt = 0; kt <= qt; kt++) {
        CP_WAIT1();          // Q + K[kt] resident (V[kt] may be in flight)
        __syncthreads();

        float sacc[16][4];
        #pragma unroll
        for (int n = 0; n < 16; n++)
            #pragma unroll
            for (int i = 0; i < 4; i++) sacc[n][i] = 0.f;

        #pragma unroll
        for (int kk = 0; kk < 8; kk++) {
            uint32_t ah[4], al[4];
            ldsm_x4(ah, smem_u32(&sQh[q_r][kk*16 + q_c]));
            ldsm_x4(al, smem_u32(&sQl[q_r][kk*16 + q_c]));
            #pragma unroll
            for (int j2 = 0; j2 < 8; j2++) {
                uint32_t kb[4], klb[4];
                ldsm_x4(kb,  smem_u32(&sKh[16*j2 + k_ro][kk*16 + k_co]));
                ldsm_x4(klb, smem_u32(&sKl[16*j2 + k_ro][kk*16 + k_co]));
                // interleave the two accumulator chains (dep distance 2)
                mma16816(sacc[2*j2],   ah, kb);
                mma16816(sacc[2*j2+1], ah, kb + 2);
                mma16816(sacc[2*j2],   ah, klb);
                mma16816(sacc[2*j2+1], ah, klb + 2);
                mma16816(sacc[2*j2],   al, kb);
                mma16816(sacc[2*j2+1], al, kb + 2);
            }
        }
        __syncthreads();      // sK free

        if (kt < qt) {        // prefetch next K, overlaps softmax + PV
            const size_t kb = ((size_t)(b*SEQ + (kt+1)*128))*QKVDIM + QDIM + kh*HD;
            load_tile(sKh, QKVh + kb); load_tile(sKl, QKVl + kb); CP_COMMIT();
        }

        const bool diag = (kt == qt);
        float mx0 = -1e30f, mx1 = -1e30f;
        #pragma unroll
        for (int n = 0; n < 16; n++) {
            float e0 = sacc[n][0]*CS, e1 = sacc[n][1]*CS;
            float e2 = sacc[n][2]*CS, e3 = sacc[n][3]*CS;
            if (diag) {
                int c0 = n*8 + c_lo;
                int rr = wid*16 + r_lo;
                if (c0     > rr)     e0 = -1e30f;
                if (c0 + 1 > rr)     e1 = -1e30f;
                if (c0     > rr + 8) e2 = -1e30f;
                if (c0 + 1 > rr + 8) e3 = -1e30f;
            }
            sacc[n][0] = e0; sacc[n][1] = e1; sacc[n][2] = e2; sacc[n][3] = e3;
            mx0 = fmaxf(mx0, fmaxf(e0, e1));
            mx1 = fmaxf(mx1, fmaxf(e2, e3));
        }
        mx0 = fmaxf(mx0, __shfl_xor_sync(0xffffffffu, mx0, 1));
        mx0 = fmaxf(mx0, __shfl_xor_sync(0xffffffffu, mx0, 2));
        mx1 = fmaxf(mx1, __shfl_xor_sync(0xffffffffu, mx1, 1));
        mx1 = fmaxf(mx1, __shfl_xor_sync(0xffffffffu, mx1, 2));

        float mn0 = fmaxf(mi0, mx0), mn1 = fmaxf(mi1, mx1);
        float al0 = ex2f(mi0 - mn0), al1 = ex2f(mi1 - mn1);
        mi0 = mn0; mi1 = mn1;

        float s0 = 0.f, s1 = 0.f;
        #pragma unroll
        for (int n = 0; n < 16; n++) {
            float p0 = ex2f(sacc[n][0] - mn0), p1 = ex2f(sacc[n][1] - mn0);
            float p2 = ex2f(sacc[n][2] - mn1), p3 = ex2f(sacc[n][3] - mn1);
            sacc[n][0] = p0; sacc[n][1] = p1; sacc[n][2] = p2; sacc[n][3] = p3;
            s0 += p0 + p1; s1 += p2 + p3;
        }
        s0 += __shfl_xor_sync(0xffffffffu, s0, 1);
        s0 += __shfl_xor_sync(0xffffffffu, s0, 2);
        s1 += __shfl_xor_sync(0xffffffffu, s1, 1);
        s1 += __shfl_xor_sync(0xffffffffu, s1, 2);
        li0 = li0 * al0 + s0;
        li1 = li1 * al1 + s1;

        #pragma unroll
        for (int n = 0; n < 16; n++) {
            oacc[n][0] *= al0; oacc[n][1] *= al0;
            oacc[n][2] *= al1; oacc[n][3] *= al1;
        }

        if (kt < qt) CP_WAIT1(); else CP_WAIT0();   // V[kt] resident
        __syncthreads();

        #pragma unroll
        for (int kk2 = 0; kk2 < 8; kk2++) {
            float p00 = sacc[2*kk2][0],   p01 = sacc[2*kk2][1];
            float p02 = sacc[2*kk2][2],   p03 = sacc[2*kk2][3];
            float p10 = sacc[2*kk2+1][0], p11 = sacc[2*kk2+1][1];
            float p12 = sacc[2*kk2+1][2], p13 = sacc[2*kk2+1][3];
            uint32_t pah[4], pal[4];
            pah[0] = packbf(p00, p01); pah[1] = packbf(p02, p03);
            pah[2] = packbf(p10, p11); pah[3] = packbf(p12, p13);
            pal[0] = packbf(p00 - bf16rt(p00), p01 - bf16rt(p01));
            pal[1] = packbf(p02 - bf16rt(p02), p03 - bf16rt(p03));
            pal[2] = packbf(p10 - bf16rt(p10), p11 - bf16rt(p11));
            pal[3] = packbf(p12 - bf16rt(p12), p13 - bf16rt(p13));

            #pragma unroll
            for (int j = 0; j < 8; j++) {
                uint32_t vb[4], vlb[4];
                ldsm_x4_t(vb,  smem_u32(&sVh[kk2*16 + v_ro][16*j + v_co]));
                ldsm_x4_t(vlb, smem_u32(&sVl[kk2*16 + v_ro][16*j + v_co]));
                // interleave the two accumulator chains (dep distance 2)
                mma16816(oacc[2*j],   pah, vb);
                mma16816(oacc[2*j+1], pah, vb + 2);
                mma16816(oacc[2*j],   pah, vlb);
                mma16816(oacc[2*j+1], pah, vlb + 2);
                mma16816(oacc[2*j],   pal, vb);
                mma16816(oacc[2*j+1], pal, vb + 2);
            }
        }
        __syncthreads();      // sV free

        if (kt < qt) {        // prefetch next V, overlaps next S
            const size_t vb = ((size_t)(b*SEQ + (kt+1)*128))*QKVDIM + QDIM + KVDIM + kh*HD;
            load_tile(sVh, QKVh + vb); load_tile(sVl, QKVl + vb); CP_COMMIT();
        }
    }

    float inv0 = 1.f / li0, inv1 = 1.f / li1;
    size_t row0 = (size_t)(b*SEQ + qt*128 + wid*16 + r_lo);
    size_t colb = (size_t)h*HD + c_lo;
    #pragma unroll
    for (int n = 0; n < 16; n++) {
        float v0 = oacc[n][0]*inv0, v1 = oacc[n][1]*inv0;
        float v2 = oacc[n][2]*inv1, v3 = oacc[n][3]*inv1;
        size_t o0 = row0*QDIM + colb + n*8;
        size_t o1 = (row0+8)*QDIM + colb + n*8;
        *(uint32_t*)&AOh[o0] = packbf(bf16rt(v0), bf16rt(v1));
        *(uint32_t*)&AOl[o0] = packbf(v0 - bf16rt(v0), v1 - bf16rt(v1));
        *(uint32_t*)&AOh[o1] = packbf(bf16rt(v2), bf16rt(v3));
        *(uint32_t*)&AOl[o1] = packbf(v2 - bf16rt(v2), v3 - bf16rt(v3));
    }
}

// ---------------- launch -----------------------------------------------------
extern "C" void kernel_launch(void* const* d_in, const int* in_sizes, int n_in,
                              void* d_out, int out_size)
{
    const float* x     = (const float*)d_in[0];
    const float* wq    = (const float*)d_in[1];
    const float* wk    = (const float*)d_in[2];
    const float* wv    = (const float*)d_in[3];
    const float* wo    = (const float*)d_in[4];
    const float* freqs = (const float*)d_in[5];
    (void)in_sizes; (void)n_in; (void)out_size;

    float* out  = (float*)d_out;
    float* outk = out  + (size_t)MTOT*HIDDEN;
    float* outv = outk + (size_t)MTOT*KVDIM;

    __nv_bfloat16 *Xh, *Xl, *Wh, *Wl, *WOh, *WOl, *AOh, *AOl, *QKVh, *QKVl;
    cudaGetSymbolAddress((void**)&Xh,   g_Xh);
    cudaGetSymbolAddress((void**)&Xl,   g_Xl);
    cudaGetSymbolAddress((void**)&Wh,   g_Wh);
    cudaGetSymbolAddress((void**)&Wl,   g_Wl);
    cudaGetSymbolAddress((void**)&WOh,  g_WOh);
    cudaGetSymbolAddress((void**)&WOl,  g_WOl);
    cudaGetSymbolAddress((void**)&AOh,  g_AOh);
    cudaGetSymbolAddress((void**)&AOl,  g_AOl);
    cudaGetSymbolAddress((void**)&QKVh, g_QKVh);
    cudaGetSymbolAddress((void**)&QKVl, g_QKVl);

    cudaFuncSetAttribute(k_flash,        cudaFuncAttributeMaxDynamicSharedMemorySize, FLASH_SMEM);
    cudaFuncSetAttribute(mma_gemm<true>, cudaFuncAttributeMaxDynamicSharedMemorySize, GEMM_SMEM);
    cudaFuncSetAttribute(mma_gemm<false>,cudaFuncAttributeMaxDynamicSharedMemorySize, GEMM_SMEM);

    // 1. one fused hi/lo split of all inputs & weights
    k_split_all<<<(N4_TOT + 255)/256, 256>>>(x, wq, wk, wv, wo, Xh, Xl, Wh, Wl, WOh, WOl);

    // 2. fused QKV projection + RoPE + kv-cache outputs + bf16 hi/lo emit
    mma_gemm<true><<<dim3(QKVDIM/128, MTOT/128), 256, GEMM_SMEM>>>(
        Xh, Xl, Wh, Wl, nullptr, 0, HIDDEN, freqs, outk, outv, QKVh, QKVl);

    // 3. fused flash attention -> AOh/AOl
    k_flash<<<dim3(SEQ/128, BATCH*NH), 256, FLASH_SMEM>>>(QKVh, QKVl, AOh, AOl);

    // 4. output projection
    mma_gemm<false><<<dim3(HIDDEN/128, MTOT/128), 256, GEMM_SMEM>>>(
        AOh, AOl, WOh, WOl, out, HIDDEN, QDIM, nullptr, nullptr, nullptr, nullptr, nullptr);
}